// round 11
// baseline (speedup 1.0000x reference)
#include <cuda_runtime.h>
#include <cstdint>

// Problem constants (B=256, T=2048, D=128)
#define BB 256
#define TT 2048
#define DD 128
#define MM (BB * TT)

// Scratch: [m][3][128] fp32 : j=0 -> E = X@We^T + be
//                             j=1 -> L = sigmoid(X@Wl^T + bl)
//                             j=2 -> W = sigmoid(X@Ww^T + bw)
__device__ float g_elw[(size_t)MM * 384];

// ---------------------------------------------------------------------------
// helpers
// ---------------------------------------------------------------------------
__device__ __forceinline__ uint32_t f2tf(float f) {
    uint32_t r;
    asm("cvt.rna.tf32.f32 %0, %1;" : "=r"(r) : "f"(f));
    return r;
}

__device__ __forceinline__ unsigned long long ffma2(unsigned long long a,
                                                    unsigned long long b,
                                                    unsigned long long c) {
    unsigned long long d;
    asm("fma.rn.f32x2 %0, %1, %2, %3;" : "=l"(d) : "l"(a), "l"(b), "l"(c));
    return d;
}

__device__ __forceinline__ float2 u2f2(unsigned long long v) {
    float2 r;
    asm("mov.b64 {%0,%1}, %2;" : "=f"(r.x), "=f"(r.y) : "l"(v));
    return r;
}

__device__ __forceinline__ float tanh_approx(float x) {
    float y;
    asm("tanh.approx.f32 %0, %1;" : "=f"(y) : "f"(x));
    return y;
}

// ---------------------------------------------------------------------------
// Kernel 1: fused 3-way projection GEMM (tf32 mma.sync), bias+sigmoid epilogue
// (unchanged from round 7 — known good, ~590us; next optimization target)
// ---------------------------------------------------------------------------
__global__ __launch_bounds__(256) void proj_kernel(
    const float* __restrict__ X,
    const float* __restrict__ We, const float* __restrict__ be,
    const float* __restrict__ Wl, const float* __restrict__ bl,
    const float* __restrict__ Ww, const float* __restrict__ bw)
{
    extern __shared__ uint32_t smem[];
    uint32_t* Xs = smem;                 // [64][132] tf32
    uint32_t* Ws = smem + 64 * 132;      // [128][68] tf32

    const int tid  = threadIdx.x;
    const int warp = tid >> 5;
    const int lane = tid & 31;
    const int g    = lane >> 2;          // 0..7
    const int c    = lane & 3;           // 0..3
    const int mt   = warp & 3;           // m-tile (16 rows)
    const int nh   = warp >> 2;          // n-half (64 cols)
    const long m0  = (long)blockIdx.x * 64;
    const int r0   = mt * 16 + g;

    const float4* X4 = (const float4*)(X + m0 * DD);
    #pragma unroll
    for (int i = 0; i < 8; i++) {
        int idx = tid + i * 256;
        int row = idx >> 5;
        int c4  = idx & 31;
        float4 v = X4[row * 32 + c4];
        uint4 u = make_uint4(f2tf(v.x), f2tf(v.y), f2tf(v.z), f2tf(v.w));
        *(uint4*)&Xs[row * 132 + c4 * 4] = u;
    }

    float acc[8][4];

    #pragma unroll 1
    for (int s = 0; s < 6; s++) {
        const int j  = s >> 1;
        const int kc = s & 1;
        const float* Wj = (j == 0) ? We : ((j == 1) ? Wl : Ww);

        if (kc == 0) {
            #pragma unroll
            for (int nt = 0; nt < 8; nt++)
                #pragma unroll
                for (int q = 0; q < 4; q++) acc[nt][q] = 0.0f;
        }

        __syncthreads();

        #pragma unroll
        for (int i = 0; i < 8; i++) {
            int idx = tid + i * 256;
            int row = idx >> 4;
            int c4  = idx & 15;
            float4 v = *(const float4*)&Wj[row * 128 + kc * 64 + c4 * 4];
            uint4 u = make_uint4(f2tf(v.x), f2tf(v.y), f2tf(v.z), f2tf(v.w));
            *(uint4*)&Ws[row * 68 + c4 * 4] = u;
        }
        __syncthreads();

        #pragma unroll
        for (int kt = 0; kt < 8; kt++) {
            const int kx = kc * 64 + kt * 8 + c;
            uint32_t a0 = Xs[r0 * 132 + kx];
            uint32_t a1 = Xs[(r0 + 8) * 132 + kx];
            uint32_t a2 = Xs[r0 * 132 + kx + 4];
            uint32_t a3 = Xs[(r0 + 8) * 132 + kx + 4];
            #pragma unroll
            for (int nt = 0; nt < 8; nt++) {
                int n  = nh * 64 + nt * 8 + g;
                int kk = kt * 8 + c;
                uint32_t b0 = Ws[n * 68 + kk];
                uint32_t b1 = Ws[n * 68 + kk + 4];
                asm volatile(
                    "mma.sync.aligned.m16n8k8.row.col.f32.tf32.tf32.f32 "
                    "{%0,%1,%2,%3}, {%4,%5,%6,%7}, {%8,%9}, {%0,%1,%2,%3};\n"
                    : "+f"(acc[nt][0]), "+f"(acc[nt][1]),
                      "+f"(acc[nt][2]), "+f"(acc[nt][3])
                    : "r"(a0), "r"(a1), "r"(a2), "r"(a3),
                      "r"(b0), "r"(b1));
            }
        }

        if (kc == 1) {
            const float* bj = (j == 0) ? be : ((j == 1) ? bl : bw);
            long row0 = m0 + mt * 16 + g;
            #pragma unroll
            for (int nt = 0; nt < 8; nt++) {
                int col = nh * 64 + nt * 8 + 2 * c;
                float2 bb = *(const float2*)&bj[col];
                float v0 = acc[nt][0] + bb.x;
                float v1 = acc[nt][1] + bb.y;
                float v2 = acc[nt][2] + bb.x;
                float v3 = acc[nt][3] + bb.y;
                if (j > 0) {
                    v0 = 1.0f / (1.0f + __expf(-v0));
                    v1 = 1.0f / (1.0f + __expf(-v1));
                    v2 = 1.0f / (1.0f + __expf(-v2));
                    v3 = 1.0f / (1.0f + __expf(-v3));
                }
                *(float2*)&g_elw[(row0 * 3 + j) * 128 + col]       = make_float2(v0, v1);
                *(float2*)&g_elw[((row0 + 8) * 3 + j) * 128 + col] = make_float2(v2, v3);
            }
        }
    }
}

// ---------------------------------------------------------------------------
// Kernel 2: persistent recurrence, warp-internal reduction.
// 128 CTAs x 256 threads; CTA = 2 batch rows x 4 warps each.
// Warp (r,wq) owns outputs [32*wq, 32*wq+32) of row r.
// Lane l = (q = l>>3, eo = l&7): computes k-quarter q of outputs {eo+8j}.
// Partials combined with shfl.bfly(8), shfl.bfly(16); lane l is the writer
// for output e = 32*wq + l (prev belief stays in its register; STG/LDG
// coalesced). Belief double-buffered in smem; ONE named barrier per row/step.
// ev/lv/wv streamed by depth-2 register-prefetched LDG (no smem ring).
// ---------------------------------------------------------------------------
__global__ __launch_bounds__(256, 1) void recur_kernel(
    const float* __restrict__ Wp, const float* __restrict__ bp,
    float* __restrict__ out)
{
    __shared__ __align__(16) float bel[2][2][128];   // [buf][row][k]

    const int tid = threadIdx.x;
    const int r   = tid >> 7;            // row: warps 0-3 / 4-7
    const int l   = tid & 31;
    const int wq  = (tid >> 5) & 3;      // warp within row
    const int q   = l >> 3;              // k-quarter
    const int eo  = l & 7;
    const int e   = wq * 32 + l;         // writer's output index
    const long b  = (long)blockIdx.x * 2 + r;

    // Wp rows for outputs wq*32 + eo + 8j (j=0..3), k in [32q, 32q+32)
    unsigned long long wp[4][16];
    #pragma unroll
    for (int j = 0; j < 4; j++) {
        const unsigned long long* src = (const unsigned long long*)
            (Wp + (wq * 32 + 8 * j + eo) * 128 + 32 * q);
        #pragma unroll
        for (int i = 0; i < 16; i++) wp[j][i] = src[i];
    }
    const float bias = bp[e];

    bel[0][r][e] = 0.0f;
    __syncthreads();

    const float* ep = g_elw + ((long)b * TT) * 384 + e;
    float* outp = out + b * (long)TT * 128 + e;

    float ev0 = ep[0],   lv0 = ep[128],       wv0 = ep[256];
    float ev1 = ep[384], lv1 = ep[384 + 128], wv1 = ep[384 + 256];
    float belr = 0.0f;

#define RSTEP(T, EV, LV, WV) do {                                              \
    const int cur = (T) & 1;                                                   \
    const ulonglong2* bq = (const ulonglong2*)&bel[cur][r][q * 32];            \
    unsigned long long a0 = 0ull, a1 = 0ull, a2 = 0ull, a3 = 0ull;             \
    _Pragma("unroll")                                                          \
    for (int i = 0; i < 8; i++) {                                              \
        ulonglong2 bb = bq[i];                                                 \
        a0 = ffma2(wp[0][2*i], bb.x, a0); a0 = ffma2(wp[0][2*i+1], bb.y, a0);  \
        a1 = ffma2(wp[1][2*i], bb.x, a1); a1 = ffma2(wp[1][2*i+1], bb.y, a1);  \
        a2 = ffma2(wp[2][2*i], bb.x, a2); a2 = ffma2(wp[2][2*i+1], bb.y, a2);  \
        a3 = ffma2(wp[3][2*i], bb.x, a3); a3 = ffma2(wp[3][2*i+1], bb.y, a3);  \
    }                                                                          \
    float2 p0 = u2f2(a0), p1 = u2f2(a1), p2 = u2f2(a2), p3 = u2f2(a3);         \
    float s0 = p0.x + p0.y, s1 = p1.x + p1.y;                                  \
    float s2 = p2.x + p2.y, s3 = p3.x + p3.y;                                  \
    s0 += __shfl_xor_sync(0xffffffffu, s0, 8);                                 \
    s1 += __shfl_xor_sync(0xffffffffu, s1, 8);                                 \
    s2 += __shfl_xor_sync(0xffffffffu, s2, 8);                                 \
    s3 += __shfl_xor_sync(0xffffffffu, s3, 8);                                 \
    s0 += __shfl_xor_sync(0xffffffffu, s0, 16);                                \
    s1 += __shfl_xor_sync(0xffffffffu, s1, 16);                                \
    s2 += __shfl_xor_sync(0xffffffffu, s2, 16);                                \
    s3 += __shfl_xor_sync(0xffffffffu, s3, 16);                                \
    float mysum = (q == 0) ? s0 : (q == 1) ? s1 : (q == 2) ? s2 : s3;          \
    float pre  = mysum + bias + (EV);                                          \
    float cand = tanh_approx(pre);                                             \
    float nb   = (LV) * belr + (WV) * cand;                                    \
    belr = nb;                                                                 \
    outp[(long)(T) * 128] = nb;                                                \
    bel[cur ^ 1][r][e] = nb;                                                   \
    if ((T) + 2 < TT) {                                                        \
        const float* pp = ep + (long)((T) + 2) * 384;                          \
        EV = pp[0]; LV = pp[128]; WV = pp[256];                                \
    }                                                                          \
    asm volatile("bar.sync %0, 128;\n" :: "r"(r + 1) : "memory");              \
} while (0)

    for (int t = 0; t < TT; t += 2) {
        RSTEP(t,     ev0, lv0, wv0);
        RSTEP(t + 1, ev1, lv1, wv1);
    }
#undef RSTEP
}

// ---------------------------------------------------------------------------
// launch
// ---------------------------------------------------------------------------
extern "C" void kernel_launch(void* const* d_in, const int* in_sizes, int n_in,
                              void* d_out, int out_size) {
    const float* X  = (const float*)d_in[0];
    const float* We = (const float*)d_in[1];
    const float* be = (const float*)d_in[2];
    const float* Wp = (const float*)d_in[3];
    const float* bp = (const float*)d_in[4];
    const float* Wl = (const float*)d_in[5];
    const float* bl = (const float*)d_in[6];
    const float* Ww = (const float*)d_in[7];
    const float* bw = (const float*)d_in[8];
    float* out = (float*)d_out;

    // Xs (33.8KB) + Ws (34.8KB) = 68.6KB dynamic smem.
    cudaFuncSetAttribute(proj_kernel,
                         cudaFuncAttributeMaxDynamicSharedMemorySize, 68608);

    proj_kernel<<<MM / 64, 256, 68608>>>(X, We, be, Wl, bl, Ww, bw);
    recur_kernel<<<BB / 2, 256>>>(Wp, bp, out);
}

// round 15
// speedup vs baseline: 1.0431x; 1.0431x over previous
#include <cuda_runtime.h>
#include <cstdint>

// Problem constants (B=256, T=2048, D=128)
#define BB 256
#define TT 2048
#define DD 128
#define CH 16              // timesteps per ring chunk
#define NCH (TT / CH)      // 128 chunks

typedef unsigned long long ull;

// ---------------------------------------------------------------------------
// dynamic smem layout (bytes)
//   Bfrag : 0      .. 98304   12288 ull  fp16 B-fragments, mma-lane order
//   ring  : 98304  .. 196608  24576 f32  [2 slot][16 tl][2 rr][384 = E|L|W]
//   sbias : 196608 .. 198144  384 f32    [j*128 + n]
//   bel   : 198144 .. 200192  512 f32    [2 buf][2 r][128]
//   mbar  : 200192 .. 200224  4 ull      full[2], empty[2]
// ---------------------------------------------------------------------------
#define SM_BFRAG 0
#define SM_RING  98304
#define SM_BIAS  196608
#define SM_BEL   198144
#define SM_MBAR  200192
#define SMEM_BYTES 200704

// ---------------------------------------------------------------------------
// helpers
// ---------------------------------------------------------------------------
__device__ __forceinline__ ull ffma2(ull a, ull b, ull c) {
    ull d;
    asm("fma.rn.f32x2 %0, %1, %2, %3;" : "=l"(d) : "l"(a), "l"(b), "l"(c));
    return d;
}

__device__ __forceinline__ float2 u2f2(ull v) {
    float2 r;
    asm("mov.b64 {%0,%1}, %2;" : "=f"(r.x), "=f"(r.y) : "l"(v));
    return r;
}

__device__ __forceinline__ float tanh_approx(float x) {
    float y;
    asm("tanh.approx.f32 %0, %1;" : "=f"(y) : "f"(x));
    return y;
}

// pack two f32 into f16x2: element0(lo)=lo, element1(hi)=hi
// (PTX cvt packs FIRST source into the HIGH half)
__device__ __forceinline__ uint32_t h2(float lo, float hi) {
    uint32_t d;
    asm("cvt.rn.f16x2.f32 %0, %1, %2;" : "=r"(d) : "f"(hi), "f"(lo));
    return d;
}

__device__ __forceinline__ uint32_t sptr(const void* p) {
    return (uint32_t)__cvta_generic_to_shared(p);
}

__device__ __forceinline__ void mbar_init(uint32_t a, uint32_t cnt) {
    asm volatile("mbarrier.init.shared.b64 [%0], %1;" :: "r"(a), "r"(cnt) : "memory");
}
__device__ __forceinline__ void mbar_arrive(uint32_t a) {
    asm volatile("mbarrier.arrive.shared.b64 _, [%0];" :: "r"(a) : "memory");
}
__device__ __forceinline__ void mbar_wait(uint32_t a, uint32_t phase) {
    uint32_t done;
    asm volatile(
        "{\n\t.reg .pred p;\n\t"
        "mbarrier.try_wait.parity.acquire.cta.shared::cta.b64 p, [%1], %2;\n\t"
        "selp.b32 %0, 1, 0, p;\n\t}"
        : "=r"(done) : "r"(a), "r"(phase) : "memory");
    if (!done) {
        asm volatile(
            "{\n\t.reg .pred P1;\n\t"
            "WL_%=:\n\t"
            "mbarrier.try_wait.parity.acquire.cta.shared::cta.b64 P1, [%0], %1, 0x989680;\n\t"
            "@P1 bra WD_%=;\n\t"
            "bra.uni WL_%=;\n\t"
            "WD_%=:\n\t}"
            :: "r"(a), "r"(phase) : "memory");
    }
}

// ---------------------------------------------------------------------------
// Fused persistent kernel. 128 CTAs x 384 threads.
//   warps 0-7  : consumers — 2 batch rows x 4 warps, r7 recurrence core
//   warps 8-11 : producers — fp16 mma projections (3 x 128-col) into smem ring
// ---------------------------------------------------------------------------
__global__ __launch_bounds__(384, 1) void fused_kernel(
    const float* __restrict__ X,
    const float* __restrict__ We, const float* __restrict__ be,
    const float* __restrict__ Wp, const float* __restrict__ bp,
    const float* __restrict__ Wl, const float* __restrict__ bl,
    const float* __restrict__ Ww, const float* __restrict__ bw,
    float* __restrict__ out)
{
    extern __shared__ __align__(16) unsigned char smem[];
    ull*   Bfrag = (ull*)(smem + SM_BFRAG);
    float* ring  = (float*)(smem + SM_RING);
    float* sbias = (float*)(smem + SM_BIAS);
    float* bel   = (float*)(smem + SM_BEL);
    ull*   mbarp = (ull*)(smem + SM_MBAR);

    const int tid  = threadIdx.x;
    const int lane = tid & 31;
    const long bb0 = (long)blockIdx.x * 2;

    const uint32_t fullb[2]  = {sptr(mbarp + 0), sptr(mbarp + 1)};
    const uint32_t emptyb[2] = {sptr(mbarp + 2), sptr(mbarp + 3)};

    // ---- one-time init: fragment-ordered fp16 weights, biases, belief ----
    for (int idx = tid; idx < 12288; idx += 384) {
        int ntf = idx >> 8;                 // flattened n-tile 0..47
        int rem = idx & 255;
        int ks  = rem >> 5;                 // k-step 0..7
        int ln  = rem & 31;
        int g   = ln >> 2, c = ln & 3;
        int j   = ntf >> 4;
        int n   = ((ntf & 15) << 3) + g;
        int k0  = ks * 16 + 2 * c;
        const float* Wj = (j == 0) ? We : ((j == 1) ? Wl : Ww);
        uint32_t lo = h2(Wj[n * 128 + k0],     Wj[n * 128 + k0 + 1]);
        uint32_t hi = h2(Wj[n * 128 + k0 + 8], Wj[n * 128 + k0 + 9]);
        Bfrag[idx] = (ull)lo | ((ull)hi << 32);
    }
    sbias[tid] = (tid < 128) ? be[tid] : (tid < 256 ? bl[tid - 128] : bw[tid - 256]);
    for (int idx = tid; idx < 512; idx += 384) bel[idx] = 0.0f;
    if (tid == 0) {
        mbar_init(fullb[0], 128);  mbar_init(fullb[1], 128);
        mbar_init(emptyb[0], 256); mbar_init(emptyb[1], 256);
    }
    __syncthreads();

    if (tid >= 256) {
        // =================== PRODUCER (warps 8-11) ===================
        const int pw = (tid - 256) >> 5;    // 0..3, each covers 12 n-tiles
        const int g  = lane >> 2, c = lane & 3;

        #pragma unroll 1
        for (int ch = 0; ch < NCH; ch++) {
            const int slot = ch & 1;
            mbar_wait(emptyb[slot], 1u ^ ((ch >> 1) & 1));
            const int t0 = ch * CH;

            #pragma unroll 1
            for (int mt = 0; mt < 2; mt++) {
                // A fragments for this m16 tile: rows m = mt*16+g, +8
                uint32_t A[8][4];
                const int row = mt * 16 + g;
                const float* xa = X + ((bb0 + (row & 1)) * TT + (t0 + (row >> 1))) * DD;
                const float* xb = xa + 4 * DD;     // row+8 -> t+4, same rr
                #pragma unroll
                for (int ks = 0; ks < 8; ks++) {
                    float2 p0 = *(const float2*)(xa + ks * 16 + 2 * c);
                    float2 p2 = *(const float2*)(xa + ks * 16 + 2 * c + 8);
                    float2 p1 = *(const float2*)(xb + ks * 16 + 2 * c);
                    float2 p3 = *(const float2*)(xb + ks * 16 + 2 * c + 8);
                    A[ks][0] = h2(p0.x, p0.y);
                    A[ks][1] = h2(p1.x, p1.y);
                    A[ks][2] = h2(p2.x, p2.y);
                    A[ks][3] = h2(p3.x, p3.y);
                }

                #pragma unroll 1
                for (int i = 0; i < 12; i++) {
                    const int ntf = pw * 12 + i;
                    const ull* bfr = Bfrag + ntf * 256 + lane;
                    float c0 = 0.f, c1 = 0.f, c2 = 0.f, c3 = 0.f;
                    #pragma unroll
                    for (int ks = 0; ks < 8; ks++) {
                        ull bb = bfr[ks * 32];
                        uint32_t b0 = (uint32_t)bb, b1 = (uint32_t)(bb >> 32);
                        asm volatile(
                            "mma.sync.aligned.m16n8k16.row.col.f32.f16.f16.f32 "
                            "{%0,%1,%2,%3}, {%4,%5,%6,%7}, {%8,%9}, {%0,%1,%2,%3};\n"
                            : "+f"(c0), "+f"(c1), "+f"(c2), "+f"(c3)
                            : "r"(A[ks][0]), "r"(A[ks][1]),
                              "r"(A[ks][2]), "r"(A[ks][3]),
                              "r"(b0), "r"(b1));
                    }
                    const int j   = ntf >> 4;
                    const int col = j * 128 + ((ntf & 15) << 3) + 2 * c;
                    float B0 = sbias[col], B1 = sbias[col + 1];
                    float v0 = c0 + B0, v1 = c1 + B1;
                    float v2 = c2 + B0, v3 = c3 + B1;
                    if (j > 0) {
                        v0 = 1.f / (1.f + __expf(-v0));
                        v1 = 1.f / (1.f + __expf(-v1));
                        v2 = 1.f / (1.f + __expf(-v2));
                        v3 = 1.f / (1.f + __expf(-v3));
                    }
                    const int tl = (mt * 16 + g) >> 1;
                    const int rr = g & 1;
                    float* rp  = ring + ((slot * 16 + tl) * 2 + rr) * 384 + col;
                    float* rp2 = ring + ((slot * 16 + tl + 4) * 2 + rr) * 384 + col;
                    rp[0]  = v0; rp[1]  = v1;      // row m   -> tl
                    rp2[0] = v2; rp2[1] = v3;      // row m+8 -> tl+4
                }
            }
            mbar_arrive(fullb[slot]);
        }
    } else {
        // =================== CONSUMER (warps 0-7) ===================
        const int r = tid >> 7;              // local batch row
        const int e = tid & 127;             // output lane
        const long b = bb0 + r;
        const int barid = r + 1;

        ull wp[64];
        const ull* wrow = (const ull*)(Wp + e * 128);
        #pragma unroll
        for (int i = 0; i < 64; i++) wp[i] = wrow[i];
        const float bias = bp[e];

        float belr = 0.0f;
        float* outp = out + b * (long)TT * DD + e;

#define CSTEP(TL, CUR) do {                                                    \
    const float* rg = rbase + (TL) * 768;                                      \
    float ev = rg[e], lv = rg[128 + e], wv = rg[256 + e];                      \
    const ulonglong2* bq = (const ulonglong2*)(bel + (CUR) * 256 + r * 128);   \
    ull a0 = 0ull, a1 = 0ull, a2 = 0ull, a3 = 0ull;                            \
    _Pragma("unroll")                                                          \
    for (int i = 0; i < 16; i++) {                                             \
        ulonglong2 b0v = bq[2 * i];                                            \
        ulonglong2 b1v = bq[2 * i + 1];                                        \
        a0 = ffma2(wp[4 * i],     b0v.x, a0);                                  \
        a1 = ffma2(wp[4 * i + 1], b0v.y, a1);                                  \
        a2 = ffma2(wp[4 * i + 2], b1v.x, a2);                                  \
        a3 = ffma2(wp[4 * i + 3], b1v.y, a3);                                  \
    }                                                                          \
    float2 p0 = u2f2(a0), p1 = u2f2(a1), p2 = u2f2(a2), p3 = u2f2(a3);         \
    float pre = ((p0.x + p0.y) + (p1.x + p1.y)) +                              \
                ((p2.x + p2.y) + (p3.x + p3.y)) + bias + ev;                   \
    float cand = tanh_approx(pre);                                             \
    float nb   = lv * belr + wv * cand;                                        \
    belr = nb;                                                                 \
    obase[(long)(TL) * 128] = nb;                                              \
    bel[((CUR) ^ 1) * 256 + r * 128 + e] = nb;                                 \
    asm volatile("bar.sync %0, 128;\n" :: "r"(barid) : "memory");              \
} while (0)

        #pragma unroll 1
        for (int ch = 0; ch < NCH; ch++) {
            const int slot = ch & 1;
            mbar_wait(fullb[slot], (ch >> 1) & 1);
            const float* rbase = ring + (slot * 32 + r) * 384;
            float* obase = outp + (long)(ch * CH) * DD;
            #pragma unroll 1
            for (int tl = 0; tl < CH; tl += 2) {
                CSTEP(tl, 0);
                CSTEP(tl + 1, 1);
            }
            mbar_arrive(emptyb[slot]);
        }
#undef CSTEP
    }
}

// ---------------------------------------------------------------------------
// launch
// ---------------------------------------------------------------------------
extern "C" void kernel_launch(void* const* d_in, const int* in_sizes, int n_in,
                              void* d_out, int out_size) {
    const float* X  = (const float*)d_in[0];
    const float* We = (const float*)d_in[1];
    const float* be = (const float*)d_in[2];
    const float* Wp = (const float*)d_in[3];
    const float* bp = (const float*)d_in[4];
    const float* Wl = (const float*)d_in[5];
    const float* bl = (const float*)d_in[6];
    const float* Ww = (const float*)d_in[7];
    const float* bw = (const float*)d_in[8];
    float* out = (float*)d_out;

    cudaFuncSetAttribute(fused_kernel,
                         cudaFuncAttributeMaxDynamicSharedMemorySize, SMEM_BYTES);

    fused_kernel<<<BB / 2, 384, SMEM_BYTES>>>(
        X, We, be, Wp, bp, Wl, bl, Ww, bw, out);
}